// round 1
// baseline (speedup 1.0000x reference)
#include <cuda_runtime.h>
#include <cstdint>
#include <cstddef>

// Problem constants
#define NM 4
#define NB 2048
#define ND 1024
#define NE 8
#define NO 1024
#define NC 2

// Scratch (no allocations allowed): V table [d][e*2+c] and bias dots [e*2+c]
__device__ float g_vtab[ND * NE * NC];   // 16384 floats = 64 KB
__device__ float g_bdot[NE * NC];        // 16 floats

// ---------------------------------------------------------------------------
// Pass A: V[e,d,c] = sum_o expert_w[e,d,o] * head_w[o,c]
// One warp per (e,d) row (8192 rows), 4 rows per warp, expert_w read once.
// head_w slices pre-hoisted to registers (fixed per lane across rows).
// ---------------------------------------------------------------------------
__global__ void __launch_bounds__(256) build_vtab_kernel(
    const float* __restrict__ expert_w,
    const float* __restrict__ head_w)
{
    __shared__ float hw[NO * NC];  // 2048 floats
    for (int i = threadIdx.x; i < NO * NC; i += blockDim.x) hw[i] = head_w[i];
    __syncthreads();

    int lane = threadIdx.x & 31;
    int gwarp = (blockIdx.x * blockDim.x + threadIdx.x) >> 5;  // 0..2047

    // lane's o indices: o = i*128 + lane*4 + {0..3}, i = 0..7 (fixed)
    float4 hwa[8], hwb[8];
    const float4* hw4 = (const float4*)hw;
#pragma unroll
    for (int i = 0; i < 8; i++) {
        hwa[i] = hw4[i * 64 + lane * 2];
        hwb[i] = hw4[i * 64 + lane * 2 + 1];
    }

    for (int r = gwarp; r < NE * ND; r += 2048) {           // r = e*1024 + d
        const float4* row4 = (const float4*)(expert_w + ((size_t)r << 10));
        float a0 = 0.f, a1 = 0.f;
#pragma unroll
        for (int i = 0; i < 8; i++) {
            float4 w = row4[i * 32 + lane];
            a0 += w.x * hwa[i].x + w.y * hwa[i].z + w.z * hwb[i].x + w.w * hwb[i].z;
            a1 += w.x * hwa[i].y + w.y * hwa[i].w + w.z * hwb[i].y + w.w * hwb[i].w;
        }
#pragma unroll
        for (int off = 16; off; off >>= 1) {
            a0 += __shfl_down_sync(0xffffffffu, a0, off);
            a1 += __shfl_down_sync(0xffffffffu, a1, off);
        }
        if (lane == 0) {
            int e = r >> 10, d = r & 1023;
            g_vtab[(d << 4) + (e << 1) + 0] = a0;
            g_vtab[(d << 4) + (e << 1) + 1] = a1;
        }
    }
}

// ---------------------------------------------------------------------------
// bdot[e,c] = sum_o expert_b[e,o] * head_w[o,c]   (8 blocks, one per expert)
// ---------------------------------------------------------------------------
__global__ void __launch_bounds__(256) build_bdot_kernel(
    const float* __restrict__ expert_b,
    const float* __restrict__ head_w)
{
    __shared__ float r0[256], r1[256];
    int e = blockIdx.x;
    int tid = threadIdx.x;
    float a0 = 0.f, a1 = 0.f;
    for (int o = tid; o < NO; o += 256) {
        float b = expert_b[(e << 10) + o];
        float2 h = *(const float2*)(head_w + (o << 1));
        a0 += b * h.x;
        a1 += b * h.y;
    }
    r0[tid] = a0; r1[tid] = a1;
    __syncthreads();
    for (int stp = 128; stp; stp >>= 1) {
        if (tid < stp) { r0[tid] += r0[tid + stp]; r1[tid] += r1[tid + stp]; }
        __syncthreads();
    }
    if (tid == 0) { g_bdot[e * 2] = r0[0]; g_bdot[e * 2 + 1] = r1[0]; }
}

// ---------------------------------------------------------------------------
// Main fused pass: single read of x computes gate logits (8 acc) AND all-8
// expert candidate outputs (16 acc) per token, then selects the winner.
//
// Block = 8 consecutive b values x all 4 modalities = 32 tokens, 256 threads
// = 32 tokens (lane) x 8 D-slices (warp id). gate_w / V tables in SMEM and
// read as warp-uniform broadcasts (all lanes share the same d each step).
// M-mean via shuffles; each output element written exactly once.
// ---------------------------------------------------------------------------
#define XS_STRIDE 258   // 256 + 2: even (float2-aligned stores), 2-way read conflicts only
#define RED_STRIDE 25

__global__ void __launch_bounds__(256) moe_main_kernel(
    const float* __restrict__ x,
    const float* __restrict__ gate_w,
    const float* __restrict__ gate_b,
    const float* __restrict__ head_b,
    float* __restrict__ out)
{
    extern __shared__ float sm[];
    float* gt  = sm;                    // 8192  floats: gate_w [d][e]
    float* vt  = sm + 8192;             // 16384 floats: V [d][e*2+c]
    float* xs  = sm + 24576;            // 32 * 258 = 8256 floats: x tile
    float* red = sm + 32832;            // 256 * 25 = 6400 floats

    int tid = threadIdx.x;
    int b0  = blockIdx.x << 3;          // 8 b-values per block

    // fill broadcast tables (vectorized, coalesced)
    {
        const float4* gsrc = (const float4*)gate_w;
        float4* gdst = (float4*)gt;
        for (int i = tid; i < 2048; i += 256) gdst[i] = gsrc[i];
        const float4* vsrc = (const float4*)g_vtab;
        float4* vdst = (float4*)vt;
        for (int i = tid; i < 4096; i += 256) vdst[i] = vsrc[i];
    }

    int t = tid & 31;                   // token lane: m = t>>3, brel = t&7
    int s = tid >> 5;                   // D slice 0..7

    float ga[8], va[16];
#pragma unroll
    for (int k = 0; k < 8; k++)  ga[k] = 0.f;
#pragma unroll
    for (int k = 0; k < 16; k++) va[k] = 0.f;

    for (int chunk = 0; chunk < 4; chunk++) {
        int dc = chunk << 8;
        __syncthreads();  // xs free to overwrite; also orders table fill before 1st compute
        // stage 32 rows x 256 cols of x, coalesced
        for (int v = tid; v < 2048; v += 256) {
            int r = v >> 6, c4 = v & 63;
            int row = ((r >> 3) << 11) + b0 + (r & 7);      // m*2048 + b0 + brel
            float4 t4 = *(const float4*)(x + ((size_t)row << 10) + dc + (c4 << 2));
            float* dst = xs + r * XS_STRIDE + (c4 << 2);
            *(float2*)(dst)     = make_float2(t4.x, t4.y);
            *(float2*)(dst + 2) = make_float2(t4.z, t4.w);
        }
        __syncthreads();

        const float* xrow = xs + t * XS_STRIDE + (s << 5);
        int dg0 = dc + (s << 5);
#pragma unroll 4
        for (int j = 0; j < 32; j += 2) {
            float2 xv = *(const float2*)(xrow + j);
            int dg = dg0 + j;
            const float4* gp = ((const float4*)gt) + (dg << 1);
            const float4* vp = ((const float4*)vt) + (dg << 2);
            // element dg (xv.x)
            {
                float4 g0 = gp[0], g1 = gp[1];
                ga[0] += xv.x * g0.x; ga[1] += xv.x * g0.y; ga[2] += xv.x * g0.z; ga[3] += xv.x * g0.w;
                ga[4] += xv.x * g1.x; ga[5] += xv.x * g1.y; ga[6] += xv.x * g1.z; ga[7] += xv.x * g1.w;
                float4 v0 = vp[0], v1 = vp[1], v2 = vp[2], v3 = vp[3];
                va[0]  += xv.x * v0.x; va[1]  += xv.x * v0.y; va[2]  += xv.x * v0.z; va[3]  += xv.x * v0.w;
                va[4]  += xv.x * v1.x; va[5]  += xv.x * v1.y; va[6]  += xv.x * v1.z; va[7]  += xv.x * v1.w;
                va[8]  += xv.x * v2.x; va[9]  += xv.x * v2.y; va[10] += xv.x * v2.z; va[11] += xv.x * v2.w;
                va[12] += xv.x * v3.x; va[13] += xv.x * v3.y; va[14] += xv.x * v3.z; va[15] += xv.x * v3.w;
            }
            // element dg+1 (xv.y)
            {
                float4 g0 = gp[2], g1 = gp[3];
                ga[0] += xv.y * g0.x; ga[1] += xv.y * g0.y; ga[2] += xv.y * g0.z; ga[3] += xv.y * g0.w;
                ga[4] += xv.y * g1.x; ga[5] += xv.y * g1.y; ga[6] += xv.y * g1.z; ga[7] += xv.y * g1.w;
                float4 v0 = vp[4], v1 = vp[5], v2 = vp[6], v3 = vp[7];
                va[0]  += xv.y * v0.x; va[1]  += xv.y * v0.y; va[2]  += xv.y * v0.z; va[3]  += xv.y * v0.w;
                va[4]  += xv.y * v1.x; va[5]  += xv.y * v1.y; va[6]  += xv.y * v1.z; va[7]  += xv.y * v1.w;
                va[8]  += xv.y * v2.x; va[9]  += xv.y * v2.y; va[10] += xv.y * v2.z; va[11] += xv.y * v2.w;
                va[12] += xv.y * v3.x; va[13] += xv.y * v3.y; va[14] += xv.y * v3.z; va[15] += xv.y * v3.w;
            }
        }
    }

    // cross-slice reduction: 24 partials per (token, slice)
    {
        float* rp = red + tid * RED_STRIDE;   // tid == s*32 + t
#pragma unroll
        for (int k = 0; k < 8; k++)  rp[k]     = ga[k];
#pragma unroll
        for (int k = 0; k < 16; k++) rp[8 + k] = va[k];
    }
    __syncthreads();

    if (tid < 32) {
        float acc[24];
#pragma unroll
        for (int k = 0; k < 24; k++) acc[k] = red[tid * RED_STRIDE + k];
#pragma unroll
        for (int s2 = 1; s2 < 8; s2++) {
            const float* rp = red + (s2 * 32 + tid) * RED_STRIDE;
#pragma unroll
            for (int k = 0; k < 24; k++) acc[k] += rp[k];
        }
        // gate logits (+bias), winner = max index among top-2
        float g[8];
#pragma unroll
        for (int e = 0; e < 8; e++) g[e] = acc[e] + gate_b[e];
        int i1 = 0; float m1 = g[0];
#pragma unroll
        for (int e = 1; e < 8; e++) if (g[e] > m1) { m1 = g[e]; i1 = e; }
        int i2 = 0; float m2 = -3.402823466e38f;
#pragma unroll
        for (int e = 0; e < 8; e++) if (e != i1 && g[e] > m2) { m2 = g[e]; i2 = e; }
        int w = (i1 > i2) ? i1 : i2;

        float o0 = acc[8 + (w << 1) + 0] + g_bdot[(w << 1) + 0];
        float o1 = acc[8 + (w << 1) + 1] + g_bdot[(w << 1) + 1];

        // mean over modalities: lanes {brel, brel+8, brel+16, brel+24}
        o0 += __shfl_down_sync(0xffffffffu, o0, 16);
        o0 += __shfl_down_sync(0xffffffffu, o0, 8);
        o1 += __shfl_down_sync(0xffffffffu, o1, 16);
        o1 += __shfl_down_sync(0xffffffffu, o1, 8);

        if (tid < 8) {
            int b = b0 + tid;
            out[(b << 1) + 0] = 0.25f * o0 + head_b[0];
            out[(b << 1) + 1] = 0.25f * o1 + head_b[1];
        }
    }
}

// ---------------------------------------------------------------------------
extern "C" void kernel_launch(void* const* d_in, const int* in_sizes, int n_in,
                              void* d_out, int out_size)
{
    const float* x        = (const float*)d_in[0];
    const float* gate_w   = (const float*)d_in[1];
    const float* gate_b   = (const float*)d_in[2];
    const float* expert_w = (const float*)d_in[3];
    const float* expert_b = (const float*)d_in[4];
    const float* head_w   = (const float*)d_in[5];
    const float* head_b   = (const float*)d_in[6];
    float* out = (float*)d_out;

    const size_t SMEM = (8192 + 16384 + 32 * XS_STRIDE + 256 * RED_STRIDE) * sizeof(float);
    cudaFuncSetAttribute(moe_main_kernel,
                         cudaFuncAttributeMaxDynamicSharedMemorySize, (int)SMEM);

    build_vtab_kernel<<<256, 256>>>(expert_w, head_w);
    build_bdot_kernel<<<8, 256>>>(expert_b, head_w);
    moe_main_kernel<<<256, 256, SMEM>>>(x, gate_w, gate_b, head_b, out);
}

// round 2
// speedup vs baseline: 1.1645x; 1.1645x over previous
#include <cuda_runtime.h>
#include <cstdint>
#include <cstddef>

// Problem constants
#define NM 4
#define NB 2048
#define ND 1024
#define NE 8
#define NO 1024
#define NC 2

// Scratch (no allocations allowed)
__device__ float g_vtab[ND * NE * NC];   // [d][e*2+c]  64 KB
__device__ float g_bdot[NE * NC];        // 16 floats

// packed f32x2 FMA (sm_100a+; ptxas never auto-fuses this)
#define FMA_F32X2(acc, a, b) \
    asm("fma.rn.f32x2 %0, %1, %2, %0;" : "+l"(acc) : "l"(a), "l"(b))
#define BCAST_F32X2(dst, f) \
    asm("mov.b64 %0, {%1, %1};" : "=l"(dst) : "f"(f))
#define UNPACK_F32X2(lo, hi, in) \
    asm("mov.b64 {%0, %1}, %2;" : "=f"(lo), "=f"(hi) : "l"(in))

// ---------------------------------------------------------------------------
// Pass A: V[e,d,c] = sum_o expert_w[e,d,o] * head_w[o,c]
// 1024 blocks x 256 threads = 8192 warps, ONE row per warp (max MLP, low regs).
// head_w kept in SMEM (broadcast LDS) instead of registers -> high occupancy.
// bdot[e,c] fused in (blocks 0..7, warp 0).
// ---------------------------------------------------------------------------
__global__ void __launch_bounds__(256) build_vtab_kernel(
    const float* __restrict__ expert_w,
    const float* __restrict__ head_w,
    const float* __restrict__ expert_b)
{
    __shared__ float hw[NO * NC];  // 2048 floats, [o*2+c]
    for (int i = threadIdx.x; i < NO * NC; i += 256) hw[i] = head_w[i];
    __syncthreads();

    const int lane = threadIdx.x & 31;
    const int wid  = threadIdx.x >> 5;
    const int r    = (blockIdx.x << 3) + wid;          // row = e*1024 + d

    // load the full row up-front: 8 independent LDG.128
    const float4* row4 = (const float4*)(expert_w + ((size_t)r << 10));
    float4 w[8];
#pragma unroll
    for (int i = 0; i < 8; i++) w[i] = row4[i * 32 + lane];

    float a0 = 0.f, a1 = 0.f;
#pragma unroll
    for (int i = 0; i < 8; i++) {
        // o = i*128 + lane*4 + {0..3}; hw pairs at hw + 2*o
        const float4* h = (const float4*)(hw + ((i * 128 + lane * 4) << 1));
        float4 h0 = h[0], h1 = h[1];
        a0 += w[i].x * h0.x + w[i].y * h0.z + w[i].z * h1.x + w[i].w * h1.z;
        a1 += w[i].x * h0.y + w[i].y * h0.w + w[i].z * h1.y + w[i].w * h1.w;
    }
#pragma unroll
    for (int off = 16; off; off >>= 1) {
        a0 += __shfl_down_sync(0xffffffffu, a0, off);
        a1 += __shfl_down_sync(0xffffffffu, a1, off);
    }
    if (lane == 0) {
        int e = r >> 10, d = r & 1023;
        g_vtab[(d << 4) + (e << 1) + 0] = a0;
        g_vtab[(d << 4) + (e << 1) + 1] = a1;
    }

    // fused bdot: blocks 0..7, warp 0, expert e = blockIdx.x
    if (blockIdx.x < 8 && wid == 0) {
        int e = blockIdx.x;
        const float4* eb4 = ((const float4*)expert_b) + (e << 8);
        float b0 = 0.f, b1 = 0.f;
#pragma unroll
        for (int i = 0; i < 8; i++) {
            float4 bb = eb4[i * 32 + lane];
            const float4* h = (const float4*)(hw + ((i * 32 + lane) << 3));
            float4 h0 = h[0], h1 = h[1];
            b0 += bb.x * h0.x + bb.y * h0.z + bb.z * h1.x + bb.w * h1.z;
            b1 += bb.x * h0.y + bb.y * h0.w + bb.z * h1.y + bb.w * h1.w;
        }
#pragma unroll
        for (int off = 16; off; off >>= 1) {
            b0 += __shfl_down_sync(0xffffffffu, b0, off);
            b1 += __shfl_down_sync(0xffffffffu, b1, off);
        }
        if (lane == 0) { g_bdot[e * 2] = b0; g_bdot[e * 2 + 1] = b1; }
    }
}

// ---------------------------------------------------------------------------
// Main fused pass: gate logits (8 acc) + all-8 expert candidate outputs
// (16 acc) per token in ONE read of x, then winner select + m-mean.
//
// 128 blocks x 512 threads, 16 b-values x 4 modalities = 64 tokens/block.
// tid = s*64 + t: token t (lane-parallel), D-slice s (warp-uniform -> table
// reads are SMEM broadcasts). Inner loop in fma.rn.f32x2 (12 packed FMAs /
// element instead of 24 scalar), table operands loaded as ulonglong2.
// Token t -> m = t&3, brel = t>>2 so the modality mean is 4 consecutive
// lanes (pure shfl). Single wave. Every output written exactly once.
// ---------------------------------------------------------------------------
#define XS_STRIDE 258   // even (float2-aligned), mod 32 == 2 -> 2-way read conflict max
#define RED_STRIDE 25

__global__ void __launch_bounds__(512) moe_main_kernel(
    const float* __restrict__ x,
    const float* __restrict__ gate_w,
    const float* __restrict__ gate_b,
    const float* __restrict__ head_b,
    float* __restrict__ out)
{
    extern __shared__ float sm[];
    float* gt  = sm;                    // 8192  floats: gate_w [d][e]
    float* vt  = sm + 8192;             // 16384 floats: V [d][e*2+c]
    float* xs  = sm + 24576;            // 64 * 258 = 16512 floats
    float* red = sm + 41088;            // 512 * 25 = 12800 floats

    const int tid = threadIdx.x;
    const int b0  = blockIdx.x << 4;    // 16 b-values per block

    // fill broadcast tables (coalesced float4)
    {
        const float4* gsrc = (const float4*)gate_w;
        float4* gdst = (float4*)gt;
        for (int i = tid; i < 2048; i += 512) gdst[i] = gsrc[i];
        const float4* vsrc = (const float4*)g_vtab;
        float4* vdst = (float4*)vt;
        for (int i = tid; i < 4096; i += 512) vdst[i] = vsrc[i];
    }

    const int t = tid & 63;             // token: m = t&3, brel = t>>2
    const int s = tid >> 6;             // D slice 0..7 (uniform per warp)

    unsigned long long ga[4], va[8];    // packed f32x2 accumulators
#pragma unroll
    for (int k = 0; k < 4; k++) ga[k] = 0ull;
#pragma unroll
    for (int k = 0; k < 8; k++) va[k] = 0ull;

    for (int chunk = 0; chunk < 4; chunk++) {
        const int dc = chunk << 8;
        __syncthreads();  // xs reusable; also orders table fill before 1st use
        // stage 64 rows x 256 cols of x, coalesced (4096 float4 / 512 thr)
        for (int v = tid; v < 4096; v += 512) {
            int r = v >> 6, c4 = v & 63;
            int row = ((r & 3) << 11) + b0 + (r >> 2);   // m*2048 + b0 + brel
            float4 t4 = *(const float4*)(x + ((size_t)row << 10) + dc + (c4 << 2));
            float* dst = xs + r * XS_STRIDE + (c4 << 2);
            *(float2*)(dst)     = make_float2(t4.x, t4.y);
            *(float2*)(dst + 2) = make_float2(t4.z, t4.w);
        }
        __syncthreads();

        const float* xrow = xs + t * XS_STRIDE + (s << 5);
        const int dg0 = dc + (s << 5);
#pragma unroll 4
        for (int j = 0; j < 32; j += 2) {
            float2 xv = *(const float2*)(xrow + j);
            unsigned long long xx0, xx1;
            BCAST_F32X2(xx0, xv.x);
            BCAST_F32X2(xx1, xv.y);
            const int dg = dg0 + j;
            // gate table: 2 elements x 8 floats = 4 ulonglong2 (LDS.128)
            const ulonglong2* gp = (const ulonglong2*)(gt + (dg << 3));
            ulonglong2 gA = gp[0], gB = gp[1], gC = gp[2], gD = gp[3];
            FMA_F32X2(ga[0], xx0, gA.x); FMA_F32X2(ga[1], xx0, gA.y);
            FMA_F32X2(ga[2], xx0, gB.x); FMA_F32X2(ga[3], xx0, gB.y);
            FMA_F32X2(ga[0], xx1, gC.x); FMA_F32X2(ga[1], xx1, gC.y);
            FMA_F32X2(ga[2], xx1, gD.x); FMA_F32X2(ga[3], xx1, gD.y);
            // V table: 2 elements x 16 floats = 8 ulonglong2 (LDS.128)
            const ulonglong2* vp = (const ulonglong2*)(vt + (dg << 4));
            ulonglong2 v0 = vp[0], v1 = vp[1], v2 = vp[2], v3 = vp[3];
            FMA_F32X2(va[0], xx0, v0.x); FMA_F32X2(va[1], xx0, v0.y);
            FMA_F32X2(va[2], xx0, v1.x); FMA_F32X2(va[3], xx0, v1.y);
            FMA_F32X2(va[4], xx0, v2.x); FMA_F32X2(va[5], xx0, v2.y);
            FMA_F32X2(va[6], xx0, v3.x); FMA_F32X2(va[7], xx0, v3.y);
            ulonglong2 v4 = vp[4], v5 = vp[5], v6 = vp[6], v7 = vp[7];
            FMA_F32X2(va[0], xx1, v4.x); FMA_F32X2(va[1], xx1, v4.y);
            FMA_F32X2(va[2], xx1, v5.x); FMA_F32X2(va[3], xx1, v5.y);
            FMA_F32X2(va[4], xx1, v6.x); FMA_F32X2(va[5], xx1, v6.y);
            FMA_F32X2(va[6], xx1, v7.x); FMA_F32X2(va[7], xx1, v7.y);
        }
    }

    // spill 24 partials per (token, slice)
    {
        float* rp = red + tid * RED_STRIDE;
#pragma unroll
        for (int k = 0; k < 4; k++) UNPACK_F32X2(rp[2 * k], rp[2 * k + 1], ga[k]);
#pragma unroll
        for (int k = 0; k < 8; k++) UNPACK_F32X2(rp[8 + 2 * k], rp[9 + 2 * k], va[k]);
    }
    __syncthreads();

    if (tid < 64) {
        float acc[24];
#pragma unroll
        for (int k = 0; k < 24; k++) acc[k] = red[tid * RED_STRIDE + k];
#pragma unroll
        for (int s2 = 1; s2 < 8; s2++) {
            const float* rp = red + (s2 * 64 + tid) * RED_STRIDE;
#pragma unroll
            for (int k = 0; k < 24; k++) acc[k] += rp[k];
        }
        // gate logits (+bias); winner = max index among top-2 (= ref semantics)
        float g[8];
#pragma unroll
        for (int e = 0; e < 8; e++) g[e] = acc[e] + gate_b[e];
        int i1 = 0; float m1 = g[0];
#pragma unroll
        for (int e = 1; e < 8; e++) if (g[e] > m1) { m1 = g[e]; i1 = e; }
        int i2 = 0; float m2 = -3.402823466e38f;
#pragma unroll
        for (int e = 0; e < 8; e++) if (e != i1 && g[e] > m2) { m2 = g[e]; i2 = e; }
        int w = (i1 > i2) ? i1 : i2;

        float o0 = acc[8 + (w << 1) + 0] + g_bdot[(w << 1) + 0];
        float o1 = acc[8 + (w << 1) + 1] + g_bdot[(w << 1) + 1];

        // modality mean: tokens t..t+3 are m=0..3 (consecutive lanes)
        o0 += __shfl_down_sync(0xffffffffu, o0, 2);
        o0 += __shfl_down_sync(0xffffffffu, o0, 1);
        o1 += __shfl_down_sync(0xffffffffu, o1, 2);
        o1 += __shfl_down_sync(0xffffffffu, o1, 1);

        if ((tid & 3) == 0) {
            int b = b0 + (tid >> 2);
            out[(b << 1) + 0] = 0.25f * o0 + head_b[0];
            out[(b << 1) + 1] = 0.25f * o1 + head_b[1];
        }
    }
}

// ---------------------------------------------------------------------------
extern "C" void kernel_launch(void* const* d_in, const int* in_sizes, int n_in,
                              void* d_out, int out_size)
{
    const float* x        = (const float*)d_in[0];
    const float* gate_w   = (const float*)d_in[1];
    const float* gate_b   = (const float*)d_in[2];
    const float* expert_w = (const float*)d_in[3];
    const float* expert_b = (const float*)d_in[4];
    const float* head_w   = (const float*)d_in[5];
    const float* head_b   = (const float*)d_in[6];
    float* out = (float*)d_out;

    const size_t SMEM = (8192 + 16384 + 64 * XS_STRIDE + 512 * RED_STRIDE) * sizeof(float);
    cudaFuncSetAttribute(moe_main_kernel,
                         cudaFuncAttributeMaxDynamicSharedMemorySize, (int)SMEM);

    build_vtab_kernel<<<1024, 256>>>(expert_w, head_w, expert_b);
    moe_main_kernel<<<128, 512, SMEM>>>(x, gate_w, gate_b, head_b, out);
}

// round 5
// speedup vs baseline: 1.3628x; 1.1704x over previous
#include <cuda_runtime.h>
#include <cstdint>
#include <cstddef>

// Problem constants
#define NM 4
#define NB 2048
#define ND 1024
#define NE 8
#define NO 1024
#define NC 2

// Scratch (no allocations allowed)
__device__ float g_vtab[ND * NE * NC];   // [d][e*2+c]  64 KB
__device__ float g_bdot[NE * NC];        // 16 floats

// packed f32x2 FMA (sm_100a+; ptxas never auto-fuses this)
#define FMA_F32X2(acc, a, b) \
    asm("fma.rn.f32x2 %0, %1, %2, %0;" : "+l"(acc) : "l"(a), "l"(b))
#define BCAST_F32X2(dst, f) \
    asm("mov.b64 %0, {%1, %1};" : "=l"(dst) : "f"(f))
#define UNPACK_F32X2(lo, hi, in) \
    asm("mov.b64 {%0, %1}, %2;" : "=f"(lo), "=f"(hi) : "l"(in))

// ---------------------------------------------------------------------------
// Pass A: V[e,d,c] = sum_o expert_w[e,d,o] * head_w[o,c]
// 1024 blocks x 256 threads, one row per warp (max MLP). bdot fused.
// Measured ~5us, near the 32MB stream floor.
// ---------------------------------------------------------------------------
__global__ void __launch_bounds__(256) build_vtab_kernel(
    const float* __restrict__ expert_w,
    const float* __restrict__ head_w,
    const float* __restrict__ expert_b)
{
    __shared__ float hw[NO * NC];  // 2048 floats, [o*2+c]
    for (int i = threadIdx.x; i < NO * NC; i += 256) hw[i] = head_w[i];
    __syncthreads();

    const int lane = threadIdx.x & 31;
    const int wid  = threadIdx.x >> 5;
    const int r    = (blockIdx.x << 3) + wid;          // row = e*1024 + d

    const float4* row4 = (const float4*)(expert_w + ((size_t)r << 10));
    float4 w[8];
#pragma unroll
    for (int i = 0; i < 8; i++) w[i] = row4[i * 32 + lane];

    float a0 = 0.f, a1 = 0.f;
#pragma unroll
    for (int i = 0; i < 8; i++) {
        const float4* h = (const float4*)(hw + ((i * 128 + lane * 4) << 1));
        float4 h0 = h[0], h1 = h[1];
        a0 += w[i].x * h0.x + w[i].y * h0.z + w[i].z * h1.x + w[i].w * h1.z;
        a1 += w[i].x * h0.y + w[i].y * h0.w + w[i].z * h1.y + w[i].w * h1.w;
    }
#pragma unroll
    for (int off = 16; off; off >>= 1) {
        a0 += __shfl_down_sync(0xffffffffu, a0, off);
        a1 += __shfl_down_sync(0xffffffffu, a1, off);
    }
    if (lane == 0) {
        int e = r >> 10, d = r & 1023;
        g_vtab[(d << 4) + (e << 1) + 0] = a0;
        g_vtab[(d << 4) + (e << 1) + 1] = a1;
    }

    if (blockIdx.x < 8 && wid == 0) {
        int e = blockIdx.x;
        const float4* eb4 = ((const float4*)expert_b) + (e << 8);
        float b0 = 0.f, b1 = 0.f;
#pragma unroll
        for (int i = 0; i < 8; i++) {
            float4 bb = eb4[i * 32 + lane];
            const float4* h = (const float4*)(hw + ((i * 32 + lane) << 3));
            float4 h0 = h[0], h1 = h[1];
            b0 += bb.x * h0.x + bb.y * h0.z + bb.z * h1.x + bb.w * h1.z;
            b1 += bb.x * h0.y + bb.y * h0.w + bb.z * h1.y + bb.w * h1.w;
        }
#pragma unroll
        for (int off = 16; off; off >>= 1) {
            b0 += __shfl_down_sync(0xffffffffu, b0, off);
            b1 += __shfl_down_sync(0xffffffffu, b1, off);
        }
        if (lane == 0) { g_bdot[e * 2] = b0; g_bdot[e * 2 + 1] = b1; }
    }
}

// ---------------------------------------------------------------------------
// Main fused pass: TWO tokens per thread to amortize table broadcasts (the
// measured L1 bottleneck: 12 broadcast LDS.128 per iteration previously fed
// 24 FFMA2; now they feed 48).
//
// 128 blocks x 512 threads. Block = 16 b-values x 4 modalities = 64 tokens.
// Token q (0..63): m = q&3, brel = q>>2. Thread (s, t): s = tid>>5 (16
// d-slices of 64 elems), t = tid&31; handles tokens q=t (group A) and
// q=t+32 (group B). Tables in smem read as warp-uniform broadcasts.
// Reduction: two-phase through red aliased onto xs (smem 164 KB).
// ---------------------------------------------------------------------------
#define XS_STRIDE 258   // even (float2 aligned); mod 32 == 2 -> 2-way read conflict
#define RED_STRIDE 49   // odd -> conflict-free phase reads

__global__ void __launch_bounds__(512) moe_main_kernel(
    const float* __restrict__ x,
    const float* __restrict__ gate_w,
    const float* __restrict__ gate_b,
    const float* __restrict__ head_b,
    float* __restrict__ out)
{
    extern __shared__ float sm[];
    float* gt  = sm;                    // 8192  floats: gate_w [d][e]
    float* vt  = sm + 8192;             // 16384 floats: V [d][e*2+c]
    float* xs  = sm + 24576;            // 64 * 258 = 16512 floats
    float* red = xs;                    // aliased: used after xs is dead

    const int tid = threadIdx.x;
    const int b0  = blockIdx.x << 4;    // 16 b-values per block

    // fill broadcast tables (coalesced float4)
    {
        const float4* gsrc = (const float4*)gate_w;
        float4* gdst = (float4*)gt;
        for (int i = tid; i < 2048; i += 512) gdst[i] = gsrc[i];
        const float4* vsrc = (const float4*)g_vtab;
        float4* vdst = (float4*)vt;
        for (int i = tid; i < 4096; i += 512) vdst[i] = vsrc[i];
    }

    const int t = tid & 31;             // token lane (group A = t, B = t+32)
    const int s = tid >> 5;             // d-slice 0..15 (warp-uniform)

    unsigned long long gaA[4], vaA[8], gaB[4], vaB[8];
#pragma unroll
    for (int k = 0; k < 4; k++) { gaA[k] = 0ull; gaB[k] = 0ull; }
#pragma unroll
    for (int k = 0; k < 8; k++) { vaA[k] = 0ull; vaB[k] = 0ull; }

    for (int chunk = 0; chunk < 4; chunk++) {
        const int dc = chunk << 8;
        __syncthreads();  // xs reusable; also orders table fill before 1st use
        // stage 64 rows x 256 cols of x, coalesced (4096 float4 / 512 thr)
        for (int v = tid; v < 4096; v += 512) {
            int r = v >> 6, c4 = v & 63;
            int row = ((r & 3) << 11) + b0 + (r >> 2);   // m*2048 + b0 + brel
            float4 t4 = *(const float4*)(x + ((size_t)row << 10) + dc + (c4 << 2));
            float* dst = xs + r * XS_STRIDE + (c4 << 2);
            *(float2*)(dst)     = make_float2(t4.x, t4.y);
            *(float2*)(dst + 2) = make_float2(t4.z, t4.w);
        }
        __syncthreads();

        const float* xA = xs + t * XS_STRIDE + (s << 4);
        const float* xB = xA + 32 * XS_STRIDE;
        const int dg0 = dc + (s << 4);
#pragma unroll
        for (int j = 0; j < 16; j += 2) {
            float2 xa = *(const float2*)(xA + j);
            float2 xb = *(const float2*)(xB + j);
            unsigned long long a0, a1, b0p, b1p;
            BCAST_F32X2(a0, xa.x); BCAST_F32X2(a1, xa.y);
            BCAST_F32X2(b0p, xb.x); BCAST_F32X2(b1p, xb.y);
            const int dg = dg0 + j;

            // gate table: elems dg, dg+1 -> 4 x LDS.128, feeds 16 FFMA2
            {
                const ulonglong2* gp = (const ulonglong2*)(gt + (dg << 3));
                ulonglong2 gA = gp[0], gB = gp[1], gC = gp[2], gD = gp[3];
                FMA_F32X2(gaA[0], a0, gA.x); FMA_F32X2(gaA[1], a0, gA.y);
                FMA_F32X2(gaA[2], a0, gB.x); FMA_F32X2(gaA[3], a0, gB.y);
                FMA_F32X2(gaB[0], b0p, gA.x); FMA_F32X2(gaB[1], b0p, gA.y);
                FMA_F32X2(gaB[2], b0p, gB.x); FMA_F32X2(gaB[3], b0p, gB.y);
                FMA_F32X2(gaA[0], a1, gC.x); FMA_F32X2(gaA[1], a1, gC.y);
                FMA_F32X2(gaA[2], a1, gD.x); FMA_F32X2(gaA[3], a1, gD.y);
                FMA_F32X2(gaB[0], b1p, gC.x); FMA_F32X2(gaB[1], b1p, gC.y);
                FMA_F32X2(gaB[2], b1p, gD.x); FMA_F32X2(gaB[3], b1p, gD.y);
            }
            // V table elem dg: 4 x LDS.128, feeds 16 FFMA2
            {
                const ulonglong2* vp = (const ulonglong2*)(vt + (dg << 4));
                ulonglong2 v0 = vp[0], v1 = vp[1], v2 = vp[2], v3 = vp[3];
                FMA_F32X2(vaA[0], a0, v0.x); FMA_F32X2(vaA[1], a0, v0.y);
                FMA_F32X2(vaA[2], a0, v1.x); FMA_F32X2(vaA[3], a0, v1.y);
                FMA_F32X2(vaA[4], a0, v2.x); FMA_F32X2(vaA[5], a0, v2.y);
                FMA_F32X2(vaA[6], a0, v3.x); FMA_F32X2(vaA[7], a0, v3.y);
                FMA_F32X2(vaB[0], b0p, v0.x); FMA_F32X2(vaB[1], b0p, v0.y);
                FMA_F32X2(vaB[2], b0p, v1.x); FMA_F32X2(vaB[3], b0p, v1.y);
                FMA_F32X2(vaB[4], b0p, v2.x); FMA_F32X2(vaB[5], b0p, v2.y);
                FMA_F32X2(vaB[6], b0p, v3.x); FMA_F32X2(vaB[7], b0p, v3.y);
            }
            // V table elem dg+1: 4 x LDS.128, feeds 16 FFMA2
            {
                const ulonglong2* vp = (const ulonglong2*)(vt + ((dg + 1) << 4));
                ulonglong2 v4 = vp[0], v5 = vp[1], v6 = vp[2], v7 = vp[3];
                FMA_F32X2(vaA[0], a1, v4.x); FMA_F32X2(vaA[1], a1, v4.y);
                FMA_F32X2(vaA[2], a1, v5.x); FMA_F32X2(vaA[3], a1, v5.y);
                FMA_F32X2(vaA[4], a1, v6.x); FMA_F32X2(vaA[5], a1, v6.y);
                FMA_F32X2(vaA[6], a1, v7.x); FMA_F32X2(vaA[7], a1, v7.y);
                FMA_F32X2(vaB[0], b1p, v4.x); FMA_F32X2(vaB[1], b1p, v4.y);
                FMA_F32X2(vaB[2], b1p, v5.x); FMA_F32X2(vaB[3], b1p, v5.y);
                FMA_F32X2(vaB[4], b1p, v6.x); FMA_F32X2(vaB[5], b1p, v6.y);
                FMA_F32X2(vaB[6], b1p, v7.x); FMA_F32X2(vaB[7], b1p, v7.y);
            }
        }
    }

    // ---- two-phase cross-slice reduction (red aliases xs) ----
    __syncthreads();   // xs reads done everywhere

    if (s >= 8) {      // phase 1: upper slices spill 48 partials
        float* rp = red + ((s - 8) * 32 + t) * RED_STRIDE;
#pragma unroll
        for (int k = 0; k < 4; k++) UNPACK_F32X2(rp[2 * k],      rp[2 * k + 1],      gaA[k]);
#pragma unroll
        for (int k = 0; k < 8; k++) UNPACK_F32X2(rp[8 + 2 * k],  rp[9 + 2 * k],      vaA[k]);
#pragma unroll
        for (int k = 0; k < 4; k++) UNPACK_F32X2(rp[24 + 2 * k], rp[25 + 2 * k],     gaB[k]);
#pragma unroll
        for (int k = 0; k < 8; k++) UNPACK_F32X2(rp[32 + 2 * k], rp[33 + 2 * k],     vaB[k]);
    }
    __syncthreads();

    if (s < 8) {       // phase 2: lower slices combine own + paired upper slice
        float* rp = red + (s * 32 + t) * RED_STRIDE;
        float c[48];
#pragma unroll
        for (int k = 0; k < 4; k++) UNPACK_F32X2(c[2 * k],      c[2 * k + 1],      gaA[k]);
#pragma unroll
        for (int k = 0; k < 8; k++) UNPACK_F32X2(c[8 + 2 * k],  c[9 + 2 * k],      vaA[k]);
#pragma unroll
        for (int k = 0; k < 4; k++) UNPACK_F32X2(c[24 + 2 * k], c[25 + 2 * k],     gaB[k]);
#pragma unroll
        for (int k = 0; k < 8; k++) UNPACK_F32X2(c[32 + 2 * k], c[33 + 2 * k],     vaB[k]);
#pragma unroll
        for (int k = 0; k < 48; k++) c[k] += rp[k];
#pragma unroll
        for (int k = 0; k < 48; k++) rp[k] = c[k];
    }
    __syncthreads();

    if (tid < 64) {    // phase 3: final reduction over 8 slice-pairs per token
        const int q   = tid;            // token 0..63: m = q&3, brel = q>>2
        const int lt  = q & 31;
        const int off = (q >> 5) * 24;  // group A: cols 0..23, B: 24..47
        float acc[24];
#pragma unroll
        for (int k = 0; k < 24; k++) acc[k] = red[lt * RED_STRIDE + off + k];
#pragma unroll
        for (int s2 = 1; s2 < 8; s2++) {
            const float* rp = red + (s2 * 32 + lt) * RED_STRIDE + off;
#pragma unroll
            for (int k = 0; k < 24; k++) acc[k] += rp[k];
        }
        // gate logits (+bias); winner = max index among top-2 (ref semantics)
        float g[8];
#pragma unroll
        for (int e = 0; e < 8; e++) g[e] = acc[e] + gate_b[e];
        int i1 = 0; float m1 = g[0];
#pragma unroll
        for (int e = 1; e < 8; e++) if (g[e] > m1) { m1 = g[e]; i1 = e; }
        int i2 = 0; float m2 = -3.402823466e38f;
#pragma unroll
        for (int e = 0; e < 8; e++) if (e != i1 && g[e] > m2) { m2 = g[e]; i2 = e; }
        int w = (i1 > i2) ? i1 : i2;

        float o0 = acc[8 + (w << 1) + 0] + g_bdot[(w << 1) + 0];
        float o1 = acc[8 + (w << 1) + 1] + g_bdot[(w << 1) + 1];

        // modality mean: tokens q..q+3 share brel, m = q&3 (consecutive lanes)
        o0 += __shfl_down_sync(0xffffffffu, o0, 2);
        o0 += __shfl_down_sync(0xffffffffu, o0, 1);
        o1 += __shfl_down_sync(0xffffffffu, o1, 2);
        o1 += __shfl_down_sync(0xffffffffu, o1, 1);

        if ((q & 3) == 0) {
            int b = b0 + (q >> 2);
            out[(b << 1) + 0] = 0.25f * o0 + head_b[0];
            out[(b << 1) + 1] = 0.25f * o1 + head_b[1];
        }
    }
}

// ---------------------------------------------------------------------------
extern "C" void kernel_launch(void* const* d_in, const int* in_sizes, int n_in,
                              void* d_out, int out_size)
{
    const float* x        = (const float*)d_in[0];
    const float* gate_w   = (const float*)d_in[1];
    const float* gate_b   = (const float*)d_in[2];
    const float* expert_w = (const float*)d_in[3];
    const float* expert_b = (const float*)d_in[4];
    const float* head_w   = (const float*)d_in[5];
    const float* head_b   = (const float*)d_in[6];
    float* out = (float*)d_out;

    const size_t SMEM = (8192 + 16384 + 64 * XS_STRIDE) * sizeof(float);  // 164 KB
    cudaFuncSetAttribute(moe_main_kernel,
                         cudaFuncAttributeMaxDynamicSharedMemorySize, (int)SMEM);

    build_vtab_kernel<<<1024, 256>>>(expert_w, head_w, expert_b);
    moe_main_kernel<<<128, 512, SMEM>>>(x, gate_w, gate_b, head_b, out);
}